// round 13
// baseline (speedup 1.0000x reference)
#include <cuda_runtime.h>
#include <cuda_bf16.h>

// SparseToDense via inverse-gather with collision chains (R6 structure,
// 512 threads -> 100% occupancy).
//   1) memset node: g_inv[:] = -1
//   2) build: atomicExch head insert + chain link
//   3) gather: per 128-cell tile: compact active cells (+128-bit mask),
//      warp-per-cell chain-summed coalesced fill into a quad-rotated 32KB
//      tile, mask-select float4 drain. 512 threads/CTA, 4 CTAs/SM = 64 warps.
//
// SMEM tile layout: tile[c][pq][e], pq = ((sp>>2) + c) & 31, e = sp & 3.
// Drain reads physical quad = lane (linear LDS.128, conflict-free); the
// rotation folds into the STG address (quad permutation within each 512B
// segment -> fully coalesced).

#define TILE 128
#define NTHREADS 512
#define MAX_BS3 (4 * 1024 * 1024)
#define MAX_N   (4 * 1024 * 1024)
#define C64 64

__device__ int g_inv[MAX_BS3];
__device__ int g_next[MAX_N];

__global__ void build_inv(const int* __restrict__ idx, int N, int BS3) {
    int n = blockIdx.x * blockDim.x + threadIdx.x;
    if (n >= N) return;
    int r = idx[n];
    if ((unsigned)r >= (unsigned)BS3) return;       // defensive
    int old = atomicExch(&g_inv[r], n);             // push-front
    g_next[n] = old;                                // coalesced chain link
}

__global__ __launch_bounds__(NTHREADS, 4)
void gather_write(const float* __restrict__ feats,
                  const int* __restrict__ s_ptr,
                  float* __restrict__ out, int BS3) {
    __shared__ float tile[C64 * TILE];   // 32 KB, quad-rotated
    __shared__ int list_sp[TILE];
    __shared__ int list_n[TILE];
    __shared__ unsigned cellmask[4];     // bit per cell (128 bits)
    __shared__ int lcnt;

    const int S  = s_ptr[0];
    const int S3 = S * S * S;
    const int tid  = threadIdx.x;
    const int lane = tid & 31;
    const int wid  = tid >> 5;            // 0..15
    const int g0   = blockIdx.x * TILE;

    if (tid == 0) lcnt = 0;
    if (tid < 4) cellmask[tid] = 0u;
    __syncthreads();

    // Compact the active cells of this tile + build the cell mask.
    if (tid < TILE) {
        int g = g0 + tid;
        if (g < BS3) {
            int n = g_inv[g];
            if (n >= 0) {
                int p = atomicAdd(&lcnt, 1);
                list_sp[p] = tid;
                list_n[p]  = n;
                atomicOr(&cellmask[tid >> 5], 1u << (tid & 31));
            }
        }
    }
    __syncthreads();

    // Warp-per-cell feature fetch (coalesced 256B rows), chain-summed,
    // stored into the rotated tile (active cells only). ~16 cells, 16 warps
    // -> single iteration.
    for (int i = wid; i < lcnt; i += (NTHREADS >> 5)) {
        int sp = list_sp[i];
        int n  = list_n[i];
        float a0 = 0.0f, a1 = 0.0f;
        while (n >= 0) {                             // length 1 for ~99%
            const float* row = feats + (long long)n * C64;
            a0 += row[lane];
            a1 += row[lane + 32];
            n = g_next[n];                           // warp-uniform load
        }
        int sp4 = sp >> 2, e = sp & 3;
        int pq = (sp4 + lane) & 31;                  // same rotation both halves
        tile[lane * TILE + pq * 4 + e]        = a0;
        tile[(lane + 32) * TILE + pq * 4 + e] = a1;
    }
    __syncthreads();

    // Hoist mask into registers (two 64-bit halves).
    const unsigned long long m0 =
        (unsigned long long)cellmask[0] | ((unsigned long long)cellmask[1] << 32);
    const unsigned long long m1 =
        (unsigned long long)cellmask[2] | ((unsigned long long)cellmask[3] << 32);

    // Drain: warp owns 4 channels; lane reads physical quad `lane`.
    if (g0 + TILE <= BS3) {
        const int b = g0 / S3;
        const long long s3 = S3;
        float* obase = out + (long long)b * C64 * s3 + (g0 - (long long)b * s3);
        const float4* trow = reinterpret_cast<const float4*>(tile);
        #pragma unroll
        for (int i = 0; i < 4; i++) {
            int c  = wid * 4 + i;
            int lq = (lane - c) & 31;                // logical quad
            unsigned nib = (unsigned)(((lq < 16 ? m0 : m1) >> ((lq & 15) * 4))
                                      & 0xFull);
            float4 v = make_float4(0.f, 0.f, 0.f, 0.f);
            if (nib) {
                float4 t = trow[c * (TILE / 4) + lane];   // linear, no conflict
                v.x = (nib & 1u) ? t.x : 0.f;
                v.y = (nib & 2u) ? t.y : 0.f;
                v.z = (nib & 4u) ? t.z : 0.f;
                v.w = (nib & 8u) ? t.w : 0.f;
            }
            __stcs(reinterpret_cast<float4*>(obase + c * s3) + lq, v);
        }
    } else {
        // Tail fallback (unused when BS3 % TILE == 0): scalar masked writes.
        const long long s3 = S3;
        for (int sp = tid; sp < TILE; sp += NTHREADS) {
            int g = g0 + sp;
            if (g >= BS3) break;
            int b = g / S3, loc = g - b * S3;
            bool act = (cellmask[sp >> 5] >> (sp & 31)) & 1u;
            for (int c = 0; c < C64; c++) {
                int pq = ((sp >> 2) + c) & 31;
                out[(long long)b * C64 * s3 + (long long)c * s3 + loc] =
                    act ? tile[c * TILE + pq * 4 + (sp & 3)] : 0.f;
            }
        }
    }
}

extern "C" void kernel_launch(void* const* d_in, const int* in_sizes, int n_in,
                              void* d_out, int out_size) {
    const float* feats = (const float*)d_in[0];
    const int*   idx   = (const int*)d_in[1];
    const int*   s_ptr = (const int*)d_in[2];
    float*       out   = (float*)d_out;

    const int N   = in_sizes[1];           // 262144 active sites
    const int BS3 = out_size / C64;        // B * S^3 = 2M

    void* inv_ptr = nullptr;
    cudaGetSymbolAddress(&inv_ptr, g_inv);
    cudaMemsetAsync(inv_ptr, 0xFF, (size_t)BS3 * sizeof(int), 0);

    build_inv<<<(N + 255) / 256, 256>>>(idx, N, BS3);
    gather_write<<<(BS3 + TILE - 1) / TILE, NTHREADS>>>(feats, s_ptr, out, BS3);
}

// round 14
// speedup vs baseline: 1.0079x; 1.0079x over previous
#include <cuda_runtime.h>
#include <cuda_bf16.h>

// SparseToDense via inverse-gather, direct register path (no SMEM, no syncs,
// no shared atomics).
//   1) memset node: g_inv[:] = -1
//   2) build: atomicExch head insert + chain link
//   3) gather_direct: each thread owns 4 consecutive cells (heads read as one
//      coalesced int4). Channels processed in chunks of 4: active cells load
//      16B of their feature row (lane-private LDG.128, L2-resident), a 4x4
//      register transpose emits 4 STG.128 -- 512B contiguous per warp, 4KB
//      contiguous per block per channel.

#define NTHREADS 256
#define CPT 4                    // cells per thread
#define CELLS_PER_BLOCK (NTHREADS * CPT)
#define MAX_BS3 (4 * 1024 * 1024)
#define MAX_N   (4 * 1024 * 1024)
#define C64 64

__device__ __align__(16) int g_inv[MAX_BS3];
__device__ int g_next[MAX_N];

__global__ void build_inv(const int* __restrict__ idx, int N, int BS3) {
    int n = blockIdx.x * blockDim.x + threadIdx.x;
    if (n >= N) return;
    int r = idx[n];
    if ((unsigned)r >= (unsigned)BS3) return;       // defensive
    int old = atomicExch(&g_inv[r], n);             // push-front
    g_next[n] = old;                                // coalesced chain link
}

__global__ __launch_bounds__(NTHREADS, 6)
void gather_direct(const float* __restrict__ feats,
                   const int* __restrict__ s_ptr,
                   float* __restrict__ out, int BS3) {
    const int S  = s_ptr[0];
    const int S3 = S * S * S;

    const int base = blockIdx.x * CELLS_PER_BLOCK + threadIdx.x * CPT;

    if (base + CPT <= BS3) {
        // Heads of this thread's 4 cells: one coalesced LDG.128.
        int4 h = *reinterpret_cast<const int4*>(&g_inv[base]);
        const bool any = (h.x >= 0) | (h.y >= 0) | (h.z >= 0) | (h.w >= 0);
        int heads[CPT] = {h.x, h.y, h.z, h.w};

        // Quad never straddles a batch (S3 % CPT == 0).
        const int b  = base / S3;
        const int sp = base - b * S3;
        const long long s3 = S3;
        float* o = out + (long long)b * C64 * s3 + sp;

        #pragma unroll
        for (int c0 = 0; c0 < C64; c0 += 4) {
            float acc[CPT][4];
            #pragma unroll
            for (int e = 0; e < CPT; e++)
                acc[e][0] = acc[e][1] = acc[e][2] = acc[e][3] = 0.0f;

            if (any) {
                #pragma unroll
                for (int e = 0; e < CPT; e++) {
                    int n = heads[e];
                    while (n >= 0) {                 // chain length 1 for ~99%
                        float4 f = *reinterpret_cast<const float4*>(
                            feats + (long long)n * C64 + c0);
                        acc[e][0] += f.x;
                        acc[e][1] += f.y;
                        acc[e][2] += f.z;
                        acc[e][3] += f.w;
                        n = g_next[n];
                    }
                }
            }
            // 4x4 register transpose -> 4 coalesced STG.128.
            #pragma unroll
            for (int j = 0; j < 4; j++) {
                float4 v = make_float4(acc[0][j], acc[1][j],
                                       acc[2][j], acc[3][j]);
                __stcs(reinterpret_cast<float4*>(o + (long long)(c0 + j) * s3),
                       v);
            }
        }
    } else {
        // Tail fallback (unused when BS3 % CELLS_PER_BLOCK == 0).
        const long long s3 = S3;
        for (int e = 0; e < CPT; e++) {
            int g = base + e;
            if (g >= BS3) break;
            int b = g / S3, sp = g - b * S3;
            int n0 = g_inv[g];
            for (int c = 0; c < C64; c++) {
                float a = 0.0f;
                int n = n0;
                while (n >= 0) {
                    a += feats[(long long)n * C64 + c];
                    n = g_next[n];
                }
                out[((long long)b * C64 + c) * s3 + sp] = a;
            }
        }
    }
}

extern "C" void kernel_launch(void* const* d_in, const int* in_sizes, int n_in,
                              void* d_out, int out_size) {
    const float* feats = (const float*)d_in[0];
    const int*   idx   = (const int*)d_in[1];
    const int*   s_ptr = (const int*)d_in[2];
    float*       out   = (float*)d_out;

    const int N   = in_sizes[1];           // 262144 active sites
    const int BS3 = out_size / C64;        // B * S^3 = 2M

    void* inv_ptr = nullptr;
    cudaGetSymbolAddress(&inv_ptr, g_inv);
    cudaMemsetAsync(inv_ptr, 0xFF, (size_t)BS3 * sizeof(int), 0);

    build_inv<<<(N + 255) / 256, 256>>>(idx, N, BS3);

    int blocks = (BS3 + CELLS_PER_BLOCK - 1) / CELLS_PER_BLOCK;
    gather_direct<<<blocks, NTHREADS>>>(feats, s_ptr, out, BS3);
}